// round 11
// baseline (speedup 1.0000x reference)
#include <cuda_runtime.h>
#include <math.h>

#define NN 100000
#define NE 1600000

// ---- scratch (alloc-free: __device__ globals) ----
// NOTE: edge_attr is NEVER updated across processor iterations in the reference
// (e = edge_attr + mlp(...) is local to each iteration), so no edge scratch.
__device__ float g_x0[NN * 5];        // x after iteration 0
__device__ float g_x1[NN * 5];        // x after iteration 1
__device__ float g_agg[NN * 5];       // scatter accumulator
__device__ int   g_cnt[NN];           // in-degree counts

__device__ __forceinline__ float relu_(float v) { return v > 0.f ? v : 0.f; }

// ---- packed f32x2 helpers (FFMA2: 2 MACs/lane/issue; only reachable via PTX) ----
typedef unsigned long long u64;

__device__ __forceinline__ u64 pack2(float a, float b) {
    u64 r;
    asm("mov.b64 %0, {%1, %2};" : "=l"(r) : "f"(a), "f"(b));
    return r;
}
__device__ __forceinline__ void unpack2(u64 v, float& a, float& b) {
    asm("mov.b64 {%0, %1}, %2;" : "=f"(a), "=f"(b) : "l"(v));
}
__device__ __forceinline__ void fma2(u64& acc, u64 w, u64 a) {
    asm("fma.rn.f32x2 %0, %1, %2, %0;" : "+l"(acc) : "l"(w), "l"(a));
}
// 16B shared load straight into two 64-bit regs (two packed pairs)
__device__ __forceinline__ void lds_v2u64(unsigned addr, u64& a, u64& b) {
    asm("ld.shared.v2.u64 {%0, %1}, [%2];" : "=l"(a), "=l"(b) : "r"(addr));
}
// 8B shared load of an adjacent float pair, already packed
__device__ __forceinline__ u64 lds_u64(unsigned addr) {
    u64 r;
    asm("ld.shared.b64 %0, [%1];" : "=l"(r) : "r"(addr));
    return r;
}
__device__ __forceinline__ unsigned saddr_(const void* p) {
    return (unsigned)__cvta_generic_to_shared(p);
}

// ---- vectorized staging: copy n4 float4s gmem -> smem (both 16B-aligned) ----
__device__ __forceinline__ void stage4(float4* dst, const float* src, int n4, int tid, int nthr) {
    const float4* s = (const float4*)src;
    for (int i = tid; i < n4; i += nthr) dst[i] = s[i];
}

// ---- dense [K]->64, scalar h out. hin/hout MAY ALIAS (reads precede writes).
// bias_addr: shared address of 64 floats, 8B-aligned (loaded as 32 packed pairs).
template <int K>
__device__ __forceinline__ void dense_s(const float* hin, unsigned w_addr,
                                        unsigned bias_addr, float* hout) {
    u64 acc[32];
#pragma unroll
    for (int j = 0; j < 32; j++) acc[j] = lds_u64(bias_addr + j * 8);
#pragma unroll
    for (int k = 0; k < K; k++) {
        u64 aa = pack2(hin[k], hin[k]);
        unsigned base = w_addr + k * 256;
#pragma unroll
        for (int j = 0; j < 16; j++) {
            u64 w0, w1;
            lds_v2u64(base + j * 16, w0, w1);
            fma2(acc[2 * j], w0, aa);
            fma2(acc[2 * j + 1], w1, aa);
        }
    }
#pragma unroll
    for (int j = 0; j < 32; j++) {
        float a, b;
        unpack2(acc[j], a, b);
        hout[2 * j]     = relu_(a);
        hout[2 * j + 1] = relu_(b);
    }
}

// ---- dense [K]->64, PACKED relu'd h out (u64 hp[32]).
template <int K>
__device__ __forceinline__ void dense_p(const float* hin, unsigned w_addr,
                                        unsigned bias_addr, u64* hpout) {
    u64 acc[32];
#pragma unroll
    for (int j = 0; j < 32; j++) acc[j] = lds_u64(bias_addr + j * 8);
#pragma unroll
    for (int k = 0; k < K; k++) {
        u64 aa = pack2(hin[k], hin[k]);
        unsigned base = w_addr + k * 256;
#pragma unroll
        for (int j = 0; j < 16; j++) {
            u64 w0, w1;
            lds_v2u64(base + j * 16, w0, w1);
            fma2(acc[2 * j], w0, aa);
            fma2(acc[2 * j + 1], w1, aa);
        }
    }
#pragma unroll
    for (int j = 0; j < 32; j++) {
        float a, b;
        unpack2(acc[j], a, b);
        hpout[j] = pack2(relu_(a), relu_(b));
    }
}

// ---- packed 64-dot: sum_k hp[k]*w[k] + bias; w = 64 contiguous floats (16B aligned)
__device__ __forceinline__ float dot64_p(const u64* hp, unsigned w_addr, float bias) {
    u64 acc0 = 0ull, acc1 = 0ull;
#pragma unroll
    for (int j = 0; j < 16; j++) {
        u64 w0, w1;
        lds_v2u64(w_addr + j * 16, w0, w1);
        fma2(acc0, w0, hp[2 * j]);
        fma2(acc1, w1, hp[2 * j + 1]);
    }
    float a, b, c, d;
    unpack2(acc0, a, b);
    unpack2(acc1, c, d);
    return bias + ((a + b) + (c + d));
}

// ---------------------------------------------------------------- init
__global__ void zero_kernel() {
    int i = blockIdx.x * blockDim.x + threadIdx.x;
    if (i < NN) g_cnt[i] = 0;
    if (i < NN * 5) g_agg[i] = 0.f;
}

// ---------------------------------------------------------------- edge model
// Both iterations read the ORIGINAL edge_attr (reference never updates it).
// ITER==0: x from param; also builds g_cnt.   ITER==1: x = g_x0.
template <int ITER>
__global__ __launch_bounds__(128)
void edge_kernel(const float* __restrict__ x_in,
                 const float* __restrict__ ea,
                 const int* __restrict__ ei,
                 const float* __restrict__ w1, const float* __restrict__ b1,
                 const float* __restrict__ w2, const float* __restrict__ b2,
                 const float* __restrict__ w3, const float* __restrict__ b3) {
    __shared__ float4 s_w1[11 * 16];   // [11][64]
    __shared__ float4 s_w2[64 * 16];   // [64][64]
    __shared__ float4 s_w3t[5 * 16];   // transposed: [5][64], row i = w3[:,i]
    __shared__ __align__(16) float s_b1[64];
    __shared__ __align__(16) float s_b2[64];
    __shared__ float s_b3[5];

    // ---- issue the per-edge gathers FIRST (independent of smem) so their
    // DRAM/L2 latency overlaps the weight-staging phase + barrier.
    int e = blockIdx.x * blockDim.x + threadIdx.x;
    bool active = (e < NE);
    int e_c = active ? e : 0;          // clamp: inactive threads load edge 0 harmlessly

    const float* x = (ITER == 0) ? x_in : g_x0;

    int si = ei[e_c];
    int di = ei[NE + e_c];
    const float* xs = x + si * 5;
    const float* xd = x + di * 5;
    float sx0 = xs[0], sx1 = xs[1], sx2 = xs[2], sf = xs[4];
    float dx0 = xd[0], dx1 = xd[1], dx2 = xd[2], df = xd[4];
    float ea0 = ea[e_c * 5 + 0], ea1 = ea[e_c * 5 + 1], ea2 = ea[e_c * 5 + 2],
          ea3 = ea[e_c * 5 + 3], ea4 = ea[e_c * 5 + 4];

    // ---- stage weights while the gathers are in flight
    {
        int tid = threadIdx.x;
        stage4(s_w1, w1, 11 * 16, tid, blockDim.x);
        stage4(s_w2, w2, 64 * 16, tid, blockDim.x);
        stage4((float4*)s_b1, b1, 16, tid, blockDim.x);
        stage4((float4*)s_b2, b2, 16, tid, blockDim.x);
        float* p3 = (float*)s_w3t;
        for (int i = tid; i < 64 * 5; i += blockDim.x) {
            int k = i / 5, c = i % 5;
            p3[c * 64 + k] = w3[i];
        }
        if (tid < 5) s_b3[tid] = b3[tid];
    }
    __syncthreads();

    if (!active) return;

    if (ITER == 0) atomicAdd(&g_cnt[di], 1);   // in-degree

    float d0 = dx0 - sx0, d1 = dx1 - sx1, d2 = dx2 - sx2;
    float ein[11];
    ein[0] = d0; ein[1] = d1; ein[2] = d2;
    ein[3] = sqrtf(fmaf(d0, d0, fmaf(d1, d1, d2 * d2)));
    ein[4] = ea0; ein[5] = ea1; ein[6] = ea2; ein[7] = ea3; ein[8] = ea4;
    ein[9] = sf; ein[10] = df;

    float h[64];
    dense_s<11>(ein, saddr_(s_w1), saddr_(s_b1), h);   // 11 -> 64
    u64 hp[32];
    dense_p<64>(h, saddr_(s_w2), saddr_(s_b2), hp);    // 64 -> 64, packed out

    // ---- layer 3: 64 -> 5 as five packed dots over transposed rows;
    // e = edge_attr + mlp out, consumed ONLY by the scatter below.
    unsigned w3a = saddr_(s_w3t);
    float r0 = ea0 + dot64_p(hp, w3a + 0 * 256, s_b3[0]);
    float r1 = ea1 + dot64_p(hp, w3a + 1 * 256, s_b3[1]);
    float r2 = ea2 + dot64_p(hp, w3a + 2 * 256, s_b3[2]);
    float r3 = ea3 + dot64_p(hp, w3a + 3 * 256, s_b3[3]);
    float r4 = ea4 + dot64_p(hp, w3a + 4 * 256, s_b3[4]);

    float* ap = g_agg + di * 5;
    atomicAdd(ap + 0, r0);
    atomicAdd(ap + 1, r1);
    atomicAdd(ap + 2, r2);
    atomicAdd(ap + 3, r3);
    atomicAdd(ap + 4, r4);
}

// ---------------------------------------------------------------- node model
// ITER==0: x from param, writes g_x0.  ITER==1: x = g_x0, writes g_x1.
// Re-zeroes g_agg after consuming it (each element owned by exactly one thread).
template <int ITER>
__global__ __launch_bounds__(128)
void node_kernel(const float* __restrict__ x_in,
                 const float* __restrict__ w1, const float* __restrict__ b1,
                 const float* __restrict__ w2, const float* __restrict__ b2,
                 const float* __restrict__ w3, const float* __restrict__ b3) {
    __shared__ float4 s_w1[7 * 16];    // [7][64]
    __shared__ float4 s_w2[64 * 16];   // [64][64]
    __shared__ float4 s_w3[16];        // [64] final dot weights
    __shared__ __align__(16) float s_b1[64];
    __shared__ __align__(16) float s_b2[64];
    __shared__ float s_b3;

    // ---- early gathers (independent of smem)
    int n = blockIdx.x * blockDim.x + threadIdx.x;
    bool active = (n < NN);
    int n_c = active ? n : 0;

    const float* x = (ITER == 0) ? x_in : g_x0;
    float xc0 = x[n_c * 5 + 0], xc1 = x[n_c * 5 + 1], xc2 = x[n_c * 5 + 2],
          xc3 = x[n_c * 5 + 3], xc4 = x[n_c * 5 + 4];
    int c = g_cnt[n_c];
    float a0 = g_agg[n_c * 5 + 0], a1 = g_agg[n_c * 5 + 1], a2 = g_agg[n_c * 5 + 2],
          a3 = g_agg[n_c * 5 + 3], a4 = g_agg[n_c * 5 + 4];

    {
        int tid = threadIdx.x;
        stage4(s_w1, w1, 7 * 16, tid, blockDim.x);
        stage4(s_w2, w2, 64 * 16, tid, blockDim.x);
        stage4(s_w3, w3, 16, tid, blockDim.x);
        stage4((float4*)s_b1, b1, 16, tid, blockDim.x);
        stage4((float4*)s_b2, b2, 16, tid, blockDim.x);
        if (tid == 0) s_b3 = b3[0];
    }
    __syncthreads();

    if (!active) return;

    // reset accumulator for next iteration / graph replay (each element owned once)
    g_agg[n * 5 + 0] = 0.f;
    g_agg[n * 5 + 1] = 0.f;
    g_agg[n * 5 + 2] = 0.f;
    g_agg[n * 5 + 3] = 0.f;
    g_agg[n * 5 + 4] = 0.f;

    float inv = 1.0f / (float)(c > 0 ? c : 1);
    float nin[7];
    nin[0] = xc3;
    nin[1] = xc4;
    nin[2] = a0 * inv;
    nin[3] = a1 * inv;
    nin[4] = a2 * inv;
    nin[5] = a3 * inv;
    nin[6] = a4 * inv;

    float h[64];
    dense_s<7>(nin, saddr_(s_w1), saddr_(s_b1), h);    // 7 -> 64
    u64 hp[32];
    dense_p<64>(h, saddr_(s_w2), saddr_(s_b2), hp);    // 64 -> 64, packed out

    float dphi = dot64_p(hp, saddr_(s_w3), s_b3);

    float v0 = xc0, v1 = xc1, v2 = xc2, v3 = xc3, v4 = xc4 + dphi;
    float* xo = (ITER == 0) ? g_x0 : g_x1;
    xo[n * 5 + 0] = v0 + relu_(v0);
    xo[n * 5 + 1] = v1 + relu_(v1);
    xo[n * 5 + 2] = v2 + relu_(v2);
    xo[n * 5 + 3] = v3 + relu_(v3);
    xo[n * 5 + 4] = v4 + relu_(v4);
}

// ---------------------------------------------------------------- decoder
__global__ __launch_bounds__(128)
void decoder_kernel(const float* __restrict__ w1, const float* __restrict__ b1,
                    const float* __restrict__ w2, const float* __restrict__ b2,
                    const float* __restrict__ w3, const float* __restrict__ b3,
                    const float* __restrict__ w4, const float* __restrict__ b4,
                    float* __restrict__ out) {
    __shared__ float4 s_w1[5 * 16];    // [5][64]
    __shared__ float4 s_w2[64 * 16];
    __shared__ float4 s_w3[64 * 16];
    __shared__ float4 s_w4[16];        // [64]
    __shared__ __align__(16) float s_b1[64];
    __shared__ __align__(16) float s_b2[64];
    __shared__ __align__(16) float s_b3[64];
    __shared__ float s_b4;

    // ---- early gather
    int n = blockIdx.x * blockDim.x + threadIdx.x;
    bool active = (n < NN);
    int n_c = active ? n : 0;
    float xin[5];
#pragma unroll
    for (int i = 0; i < 5; i++) xin[i] = g_x1[n_c * 5 + i];

    {
        int tid = threadIdx.x;
        stage4(s_w1, w1, 5 * 16, tid, blockDim.x);
        stage4(s_w2, w2, 64 * 16, tid, blockDim.x);
        stage4(s_w3, w3, 64 * 16, tid, blockDim.x);
        stage4(s_w4, w4, 16, tid, blockDim.x);
        stage4((float4*)s_b1, b1, 16, tid, blockDim.x);
        stage4((float4*)s_b2, b2, 16, tid, blockDim.x);
        stage4((float4*)s_b3, b3, 16, tid, blockDim.x);
        if (tid == 0) s_b4 = b4[0];
    }
    __syncthreads();

    if (!active) return;

    float h[64];
    dense_s<5>(xin, saddr_(s_w1), saddr_(s_b1), h);    // 5  -> 64
    dense_s<64>(h,  saddr_(s_w2), saddr_(s_b2), h);    // 64 -> 64
    u64 hp[32];
    dense_p<64>(h,  saddr_(s_w3), saddr_(s_b3), hp);   // 64 -> 64, packed out

    out[n] = dot64_p(hp, saddr_(s_w4), s_b4);
}

// ---------------------------------------------------------------- launch
extern "C" void kernel_launch(void* const* d_in, const int* in_sizes, int n_in,
                              void* d_out, int out_size) {
    const float* x   = (const float*)d_in[0];
    const float* ea  = (const float*)d_in[1];
    const float* ew1 = (const float*)d_in[2];
    const float* eb1 = (const float*)d_in[3];
    const float* ew2 = (const float*)d_in[4];
    const float* eb2 = (const float*)d_in[5];
    const float* ew3 = (const float*)d_in[6];
    const float* eb3 = (const float*)d_in[7];
    const float* nw1 = (const float*)d_in[8];
    const float* nb1 = (const float*)d_in[9];
    const float* nw2 = (const float*)d_in[10];
    const float* nb2 = (const float*)d_in[11];
    const float* nw3 = (const float*)d_in[12];
    const float* nb3 = (const float*)d_in[13];
    const float* dw1 = (const float*)d_in[14];
    const float* db1 = (const float*)d_in[15];
    const float* dw2 = (const float*)d_in[16];
    const float* db2 = (const float*)d_in[17];
    const float* dw3 = (const float*)d_in[18];
    const float* db3 = (const float*)d_in[19];
    const float* dw4 = (const float*)d_in[20];
    const float* db4 = (const float*)d_in[21];
    const int*   ei  = (const int*)d_in[22];
    float* out = (float*)d_out;

    zero_kernel<<<(NN * 5 + 255) / 256, 256>>>();

    edge_kernel<0><<<(NE + 127) / 128, 128>>>(x, ea, ei, ew1, eb1, ew2, eb2, ew3, eb3);
    node_kernel<0><<<(NN + 127) / 128, 128>>>(x, nw1, nb1, nw2, nb2, nw3, nb3);

    edge_kernel<1><<<(NE + 127) / 128, 128>>>(x, ea, ei, ew1, eb1, ew2, eb2, ew3, eb3);
    node_kernel<1><<<(NN + 127) / 128, 128>>>(x, nw1, nb1, nw2, nb2, nw3, nb3);

    decoder_kernel<<<(NN + 127) / 128, 128>>>(dw1, db1, dw2, db2, dw3, db3, dw4, db4, out);
}

// round 12
// speedup vs baseline: 1.3557x; 1.3557x over previous
#include <cuda_runtime.h>
#include <math.h>

#define NN 100000
#define NE 1600000
#define NEH 800000   // NE/2: each edge-thread handles edges (i, i+NEH)

// ---- scratch (alloc-free: __device__ globals) ----
__device__ float g_x0[NN * 5];        // x after iteration 0
__device__ float g_x1[NN * 5];        // x after iteration 1
__device__ float g_agg[NN * 5];       // scatter accumulator
__device__ int   g_cnt[NN];           // in-degree counts

__device__ __forceinline__ float relu_(float v) { return v > 0.f ? v : 0.f; }

typedef unsigned long long u64;

__device__ __forceinline__ u64 pack2(float a, float b) {
    u64 r;
    asm("mov.b64 %0, {%1, %2};" : "=l"(r) : "f"(a), "f"(b));
    return r;
}
__device__ __forceinline__ void unpack2(u64 v, float& a, float& b) {
    asm("mov.b64 {%0, %1}, %2;" : "=f"(a), "=f"(b) : "l"(v));
}
__device__ __forceinline__ void fma2(u64& acc, u64 w, u64 a) {
    asm("fma.rn.f32x2 %0, %1, %2, %0;" : "+l"(acc) : "l"(w), "l"(a));
}
__device__ __forceinline__ void lds_v2u64(unsigned addr, u64& a, u64& b) {
    asm("ld.shared.v2.u64 {%0, %1}, [%2];" : "=l"(a), "=l"(b) : "r"(addr));
}
__device__ __forceinline__ u64 lds_u64(unsigned addr) {
    u64 r;
    asm("ld.shared.b64 %0, [%1];" : "=l"(r) : "r"(addr));
    return r;
}
__device__ __forceinline__ unsigned saddr_(const void* p) {
    return (unsigned)__cvta_generic_to_shared(p);
}

__device__ __forceinline__ void stage4(float4* dst, const float* src, int n4, int tid, int nthr) {
    const float4* s = (const float4*)src;
    for (int i = tid; i < n4; i += nthr) dst[i] = s[i];
}

// ---- single-item dense helpers (node/decoder path, unchanged from passing version)
template <int K>
__device__ __forceinline__ void dense_s(const float* hin, unsigned w_addr,
                                        unsigned bias_addr, float* hout) {
    u64 acc[32];
#pragma unroll
    for (int j = 0; j < 32; j++) acc[j] = lds_u64(bias_addr + j * 8);
#pragma unroll
    for (int k = 0; k < K; k++) {
        u64 aa = pack2(hin[k], hin[k]);
        unsigned base = w_addr + k * 256;
#pragma unroll
        for (int j = 0; j < 16; j++) {
            u64 w0, w1;
            lds_v2u64(base + j * 16, w0, w1);
            fma2(acc[2 * j], w0, aa);
            fma2(acc[2 * j + 1], w1, aa);
        }
    }
#pragma unroll
    for (int j = 0; j < 32; j++) {
        float a, b;
        unpack2(acc[j], a, b);
        hout[2 * j]     = relu_(a);
        hout[2 * j + 1] = relu_(b);
    }
}

template <int K>
__device__ __forceinline__ void dense_p(const float* hin, unsigned w_addr,
                                        unsigned bias_addr, u64* hpout) {
    u64 acc[32];
#pragma unroll
    for (int j = 0; j < 32; j++) acc[j] = lds_u64(bias_addr + j * 8);
#pragma unroll
    for (int k = 0; k < K; k++) {
        u64 aa = pack2(hin[k], hin[k]);
        unsigned base = w_addr + k * 256;
#pragma unroll
        for (int j = 0; j < 16; j++) {
            u64 w0, w1;
            lds_v2u64(base + j * 16, w0, w1);
            fma2(acc[2 * j], w0, aa);
            fma2(acc[2 * j + 1], w1, aa);
        }
    }
#pragma unroll
    for (int j = 0; j < 32; j++) {
        float a, b;
        unpack2(acc[j], a, b);
        hpout[j] = pack2(relu_(a), relu_(b));
    }
}

__device__ __forceinline__ float dot64_p(const u64* hp, unsigned w_addr, float bias) {
    u64 acc0 = 0ull, acc1 = 0ull;
#pragma unroll
    for (int j = 0; j < 16; j++) {
        u64 w0, w1;
        lds_v2u64(w_addr + j * 16, w0, w1);
        fma2(acc0, w0, hp[2 * j]);
        fma2(acc1, w1, hp[2 * j + 1]);
    }
    float a, b, c, d;
    unpack2(acc0, a, b);
    unpack2(acc1, c, d);
    return bias + ((a + b) + (c + d));
}

// ---------------------------------------------------------------- init
__global__ void zero_kernel() {
    int i = blockIdx.x * blockDim.x + threadIdx.x;
    if (i < NN) g_cnt[i] = 0;
    if (i < NN * 5) g_agg[i] = 0.f;
}

// ---------------------------------------------------------------- edge model (DUAL-EDGE)
// Each thread computes edges e and e+NEH: every broadcast weight LDS feeds 2x FMA2,
// halving l1tex wavefronts per FLOP (measured bottleneck: L1=85.8%, fma=38.6%).
// Edge-1's layer-1 activations live in per-thread smem slots to cap registers.
// Dynamic smem layout (float4 units):
//   [0,1024)  w2 | [1024,3072) h1 (8192 floats) | [3072,3248) w1 | [3248,3328) w3t | biases
#define EDGE_SMEM_BYTES (3328 * 16 + 544)

template <int ITER>
__global__ __launch_bounds__(128)
void edge_kernel(const float* __restrict__ x_in,
                 const float* __restrict__ ea,
                 const int* __restrict__ ei,
                 const float* __restrict__ w1, const float* __restrict__ b1,
                 const float* __restrict__ w2, const float* __restrict__ b2,
                 const float* __restrict__ w3, const float* __restrict__ b3) {
    extern __shared__ float4 dsm[];
    float4* s_w2  = dsm;                          // 1024 f4
    float*  s_h1  = (float*)(dsm + 1024);         // 8192 floats = [k][tid]
    float4* s_w1  = dsm + 1024 + 2048;            // 176 f4
    float4* s_w3t = dsm + 1024 + 2048 + 176;      // 80 f4 (transposed [5][64])
    float*  s_b1  = (float*)(dsm + 1024 + 2048 + 176 + 80);
    float*  s_b2  = s_b1 + 64;
    float*  s_b3  = s_b2 + 64;

    int tid  = threadIdx.x;
    int e0   = blockIdx.x * 128 + tid;            // grid is exactly NEH/128: no bounds check
    int e1   = e0 + NEH;

    const float* x = (ITER == 0) ? x_in : g_x0;

    // ---- gathers for both edges first (latency overlaps staging + barrier)
    int s0 = ei[e0], d0 = ei[NE + e0];
    int s1 = ei[e1], d1 = ei[NE + e1];
    const float* xs0 = x + s0 * 5; const float* xd0 = x + d0 * 5;
    const float* xs1 = x + s1 * 5; const float* xd1 = x + d1 * 5;
    float A_sx = xs0[0], A_sy = xs0[1], A_sz = xs0[2], A_sf = xs0[4];
    float A_dx = xd0[0], A_dy = xd0[1], A_dz = xd0[2], A_df = xd0[4];
    float B_sx = xs1[0], B_sy = xs1[1], B_sz = xs1[2], B_sf = xs1[4];
    float B_dx = xd1[0], B_dy = xd1[1], B_dz = xd1[2], B_df = xd1[4];
    const float* pe0 = ea + e0 * 5;
    const float* pe1 = ea + e1 * 5;
    float EA0[5], EA1[5];
#pragma unroll
    for (int i = 0; i < 5; i++) { EA0[i] = pe0[i]; EA1[i] = pe1[i]; }

    // ---- stage weights
    stage4(s_w2, w2, 1024, tid, 128);
    stage4(s_w1, w1, 176, tid, 128);
    {
        float* p3 = (float*)s_w3t;
        for (int i = tid; i < 64 * 5; i += 128) {
            int k = i / 5, c = i % 5;
            p3[c * 64 + k] = w3[i];
        }
        if (tid < 64) { s_b1[tid] = b1[tid]; s_b2[tid] = b2[tid]; }
        if (tid < 5) s_b3[tid] = b3[tid];
    }
    __syncthreads();

    if (ITER == 0) { atomicAdd(&g_cnt[d0], 1); atomicAdd(&g_cnt[d1], 1); }

    float ein0[11], ein1[11];
    {
        float dx = A_dx - A_sx, dy = A_dy - A_sy, dz = A_dz - A_sz;
        ein0[0] = dx; ein0[1] = dy; ein0[2] = dz;
        ein0[3] = sqrtf(fmaf(dx, dx, fmaf(dy, dy, dz * dz)));
#pragma unroll
        for (int i = 0; i < 5; i++) ein0[4 + i] = EA0[i];
        ein0[9] = A_sf; ein0[10] = A_df;
    }
    {
        float dx = B_dx - B_sx, dy = B_dy - B_sy, dz = B_dz - B_sz;
        ein1[0] = dx; ein1[1] = dy; ein1[2] = dz;
        ein1[3] = sqrtf(fmaf(dx, dx, fmaf(dy, dy, dz * dz)));
#pragma unroll
        for (int i = 0; i < 5; i++) ein1[4 + i] = EA1[i];
        ein1[9] = B_sf; ein1[10] = B_df;
    }

    unsigned w1a = saddr_(s_w1), w2a = saddr_(s_w2), w3a = saddr_(s_w3t);
    unsigned b1a = saddr_(s_b1), b2a = saddr_(s_b2);
    unsigned h1a = saddr_(s_h1) + tid * 4;   // s_h1[k*128 + tid]

    // ---- layer 1: 11 -> 64 for both edges (16 LDS feed 64 FMA2 per k)
    u64 A0[32], A1[32];
#pragma unroll
    for (int j = 0; j < 32; j++) { u64 bb = lds_u64(b1a + j * 8); A0[j] = bb; A1[j] = bb; }
#pragma unroll
    for (int k = 0; k < 11; k++) {
        u64 aa0 = pack2(ein0[k], ein0[k]);
        u64 aa1 = pack2(ein1[k], ein1[k]);
        unsigned base = w1a + k * 256;
#pragma unroll
        for (int j = 0; j < 16; j++) {
            u64 wv0, wv1;
            lds_v2u64(base + j * 16, wv0, wv1);
            fma2(A0[2 * j], wv0, aa0);     fma2(A1[2 * j], wv0, aa1);
            fma2(A0[2 * j + 1], wv1, aa0); fma2(A1[2 * j + 1], wv1, aa1);
        }
    }
    float h0[64];
#pragma unroll
    for (int j = 0; j < 32; j++) {
        float a, b;
        unpack2(A0[j], a, b);
        h0[2 * j] = relu_(a); h0[2 * j + 1] = relu_(b);
        unpack2(A1[j], a, b);
        *(float*)(s_h1 + (2 * j) * 128 + tid)     = relu_(a);
        *(float*)(s_h1 + (2 * j + 1) * 128 + tid) = relu_(b);
    }
    // private slots: no sync needed

    // ---- layer 2: 64 -> 64 for both edges
#pragma unroll
    for (int j = 0; j < 32; j++) { u64 bb = lds_u64(b2a + j * 8); A0[j] = bb; A1[j] = bb; }
#pragma unroll
    for (int k = 0; k < 64; k++) {
        u64 aa0 = pack2(h0[k], h0[k]);
        float hv;
        asm("ld.shared.f32 %0, [%1];" : "=f"(hv) : "r"(h1a + k * 512));
        u64 aa1 = pack2(hv, hv);
        unsigned base = w2a + k * 256;
#pragma unroll
        for (int j = 0; j < 16; j++) {
            u64 wv0, wv1;
            lds_v2u64(base + j * 16, wv0, wv1);
            fma2(A0[2 * j], wv0, aa0);     fma2(A1[2 * j], wv0, aa1);
            fma2(A0[2 * j + 1], wv1, aa0); fma2(A1[2 * j + 1], wv1, aa1);
        }
    }
    // relu + repack in place (A now holds packed hidden for the dots)
#pragma unroll
    for (int j = 0; j < 32; j++) {
        float a, b;
        unpack2(A0[j], a, b); A0[j] = pack2(relu_(a), relu_(b));
        unpack2(A1[j], a, b); A1[j] = pack2(relu_(a), relu_(b));
    }

    // ---- layer 3: 64 -> 5 as packed dots, both edges share weight loads
    float r0[5], r1[5];
#pragma unroll
    for (int c = 0; c < 5; c++) {
        u64 p0 = 0ull, q0 = 0ull, p1 = 0ull, q1 = 0ull;
        unsigned wa = w3a + c * 256;
#pragma unroll
        for (int j = 0; j < 16; j++) {
            u64 wv0, wv1;
            lds_v2u64(wa + j * 16, wv0, wv1);
            fma2(p0, wv0, A0[2 * j]); fma2(q0, wv1, A0[2 * j + 1]);
            fma2(p1, wv0, A1[2 * j]); fma2(q1, wv1, A1[2 * j + 1]);
        }
        float a, b, cc, d;
        unpack2(p0, a, b); unpack2(q0, cc, d);
        r0[c] = EA0[c] + s_b3[c] + ((a + b) + (cc + d));
        unpack2(p1, a, b); unpack2(q1, cc, d);
        r1[c] = EA1[c] + s_b3[c] + ((a + b) + (cc + d));
    }

    float* ap0 = g_agg + d0 * 5;
    float* ap1 = g_agg + d1 * 5;
#pragma unroll
    for (int i = 0; i < 5; i++) atomicAdd(ap0 + i, r0[i]);
#pragma unroll
    for (int i = 0; i < 5; i++) atomicAdd(ap1 + i, r1[i]);
}

// ---------------------------------------------------------------- node model (unchanged)
template <int ITER>
__global__ __launch_bounds__(128)
void node_kernel(const float* __restrict__ x_in,
                 const float* __restrict__ w1, const float* __restrict__ b1,
                 const float* __restrict__ w2, const float* __restrict__ b2,
                 const float* __restrict__ w3, const float* __restrict__ b3) {
    __shared__ float4 s_w1[7 * 16];
    __shared__ float4 s_w2[64 * 16];
    __shared__ float4 s_w3[16];
    __shared__ __align__(16) float s_b1[64];
    __shared__ __align__(16) float s_b2[64];
    __shared__ float s_b3;

    int n = blockIdx.x * blockDim.x + threadIdx.x;
    bool active = (n < NN);
    int n_c = active ? n : 0;

    const float* x = (ITER == 0) ? x_in : g_x0;
    float xc0 = x[n_c * 5 + 0], xc1 = x[n_c * 5 + 1], xc2 = x[n_c * 5 + 2],
          xc3 = x[n_c * 5 + 3], xc4 = x[n_c * 5 + 4];
    int c = g_cnt[n_c];
    float a0 = g_agg[n_c * 5 + 0], a1 = g_agg[n_c * 5 + 1], a2 = g_agg[n_c * 5 + 2],
          a3 = g_agg[n_c * 5 + 3], a4 = g_agg[n_c * 5 + 4];

    {
        int tid = threadIdx.x;
        stage4(s_w1, w1, 7 * 16, tid, blockDim.x);
        stage4(s_w2, w2, 64 * 16, tid, blockDim.x);
        stage4(s_w3, w3, 16, tid, blockDim.x);
        stage4((float4*)s_b1, b1, 16, tid, blockDim.x);
        stage4((float4*)s_b2, b2, 16, tid, blockDim.x);
        if (tid == 0) s_b3 = b3[0];
    }
    __syncthreads();

    if (!active) return;

    g_agg[n * 5 + 0] = 0.f;
    g_agg[n * 5 + 1] = 0.f;
    g_agg[n * 5 + 2] = 0.f;
    g_agg[n * 5 + 3] = 0.f;
    g_agg[n * 5 + 4] = 0.f;

    float inv = 1.0f / (float)(c > 0 ? c : 1);
    float nin[7];
    nin[0] = xc3;
    nin[1] = xc4;
    nin[2] = a0 * inv;
    nin[3] = a1 * inv;
    nin[4] = a2 * inv;
    nin[5] = a3 * inv;
    nin[6] = a4 * inv;

    float h[64];
    dense_s<7>(nin, saddr_(s_w1), saddr_(s_b1), h);
    u64 hp[32];
    dense_p<64>(h, saddr_(s_w2), saddr_(s_b2), hp);

    float dphi = dot64_p(hp, saddr_(s_w3), s_b3);

    float v0 = xc0, v1 = xc1, v2 = xc2, v3 = xc3, v4 = xc4 + dphi;
    float* xo = (ITER == 0) ? g_x0 : g_x1;
    xo[n * 5 + 0] = v0 + relu_(v0);
    xo[n * 5 + 1] = v1 + relu_(v1);
    xo[n * 5 + 2] = v2 + relu_(v2);
    xo[n * 5 + 3] = v3 + relu_(v3);
    xo[n * 5 + 4] = v4 + relu_(v4);
}

// ---------------------------------------------------------------- decoder (unchanged)
__global__ __launch_bounds__(128)
void decoder_kernel(const float* __restrict__ w1, const float* __restrict__ b1,
                    const float* __restrict__ w2, const float* __restrict__ b2,
                    const float* __restrict__ w3, const float* __restrict__ b3,
                    const float* __restrict__ w4, const float* __restrict__ b4,
                    float* __restrict__ out) {
    __shared__ float4 s_w1[5 * 16];
    __shared__ float4 s_w2[64 * 16];
    __shared__ float4 s_w3[64 * 16];
    __shared__ float4 s_w4[16];
    __shared__ __align__(16) float s_b1[64];
    __shared__ __align__(16) float s_b2[64];
    __shared__ __align__(16) float s_b3[64];
    __shared__ float s_b4;

    int n = blockIdx.x * blockDim.x + threadIdx.x;
    bool active = (n < NN);
    int n_c = active ? n : 0;
    float xin[5];
#pragma unroll
    for (int i = 0; i < 5; i++) xin[i] = g_x1[n_c * 5 + i];

    {
        int tid = threadIdx.x;
        stage4(s_w1, w1, 5 * 16, tid, blockDim.x);
        stage4(s_w2, w2, 64 * 16, tid, blockDim.x);
        stage4(s_w3, w3, 64 * 16, tid, blockDim.x);
        stage4(s_w4, w4, 16, tid, blockDim.x);
        stage4((float4*)s_b1, b1, 16, tid, blockDim.x);
        stage4((float4*)s_b2, b2, 16, tid, blockDim.x);
        stage4((float4*)s_b3, b3, 16, tid, blockDim.x);
        if (tid == 0) s_b4 = b4[0];
    }
    __syncthreads();

    if (!active) return;

    float h[64];
    dense_s<5>(xin, saddr_(s_w1), saddr_(s_b1), h);
    dense_s<64>(h,  saddr_(s_w2), saddr_(s_b2), h);
    u64 hp[32];
    dense_p<64>(h,  saddr_(s_w3), saddr_(s_b3), hp);

    out[n] = dot64_p(hp, saddr_(s_w4), s_b4);
}

// ---------------------------------------------------------------- launch
extern "C" void kernel_launch(void* const* d_in, const int* in_sizes, int n_in,
                              void* d_out, int out_size) {
    const float* x   = (const float*)d_in[0];
    const float* ea  = (const float*)d_in[1];
    const float* ew1 = (const float*)d_in[2];
    const float* eb1 = (const float*)d_in[3];
    const float* ew2 = (const float*)d_in[4];
    const float* eb2 = (const float*)d_in[5];
    const float* ew3 = (const float*)d_in[6];
    const float* eb3 = (const float*)d_in[7];
    const float* nw1 = (const float*)d_in[8];
    const float* nb1 = (const float*)d_in[9];
    const float* nw2 = (const float*)d_in[10];
    const float* nb2 = (const float*)d_in[11];
    const float* nw3 = (const float*)d_in[12];
    const float* nb3 = (const float*)d_in[13];
    const float* dw1 = (const float*)d_in[14];
    const float* db1 = (const float*)d_in[15];
    const float* dw2 = (const float*)d_in[16];
    const float* db2 = (const float*)d_in[17];
    const float* dw3 = (const float*)d_in[18];
    const float* db3 = (const float*)d_in[19];
    const float* dw4 = (const float*)d_in[20];
    const float* db4 = (const float*)d_in[21];
    const int*   ei  = (const int*)d_in[22];
    float* out = (float*)d_out;

    cudaFuncSetAttribute(edge_kernel<0>, cudaFuncAttributeMaxDynamicSharedMemorySize, EDGE_SMEM_BYTES);
    cudaFuncSetAttribute(edge_kernel<1>, cudaFuncAttributeMaxDynamicSharedMemorySize, EDGE_SMEM_BYTES);

    zero_kernel<<<(NN * 5 + 255) / 256, 256>>>();

    edge_kernel<0><<<NEH / 128, 128, EDGE_SMEM_BYTES>>>(x, ea, ei, ew1, eb1, ew2, eb2, ew3, eb3);
    node_kernel<0><<<(NN + 127) / 128, 128>>>(x, nw1, nb1, nw2, nb2, nw3, nb3);

    edge_kernel<1><<<NEH / 128, 128, EDGE_SMEM_BYTES>>>(x, ea, ei, ew1, eb1, ew2, eb2, ew3, eb3);
    node_kernel<1><<<(NN + 127) / 128, 128>>>(x, nw1, nb1, nw2, nb2, nw3, nb3);

    decoder_kernel<<<(NN + 127) / 128, 128>>>(dw1, db1, dw2, db2, dw3, db3, dw4, db4, out);
}